// round 7
// baseline (speedup 1.0000x reference)
#include <cuda_runtime.h>
#include <cstdint>

// -----------------------------------------------------------------------------
// Surv_Loss (R7): R4 quad structure, tuned occupancy/granularity.
//   - 128-thread blocks, __launch_bounds__(128,12): regs<=42 -> ~5-6 LDG.128
//     in flight per warp AND 48 warps/SM resident (R4: 32 regs choked MLP;
//     R5: occ3 choked warp count; R6: one fat wave left a drain tail).
//   - grid = 1776 CTAs = one wave at occ 12; 4-warp CTAs give fine-grained
//     scheduling. Static stride over 8192 32-row batches (deterministic).
//   - status==1 rows: lane-parallel gather issued early, consumed last.
//   - fused final reduction (threadfence last-block, double accum).
// -----------------------------------------------------------------------------

#define BLOCK_THREADS 128
#define WARPS_PER_BLOCK 4
#define NBLOCKS 1776
#define BATCH 32
#define MAX_PARTIALS 2048
#define FULL 0xFFFFFFFFu

__device__ double g_partials[MAX_PARTIALS];
__device__ unsigned int g_count = 0;

// Pop up to 4 set bits from m; issue the predicated float4 load wave for those
// rows. All 32 lanes participate (m is warp-uniform).
__device__ __forceinline__ void quad_issue(
    const float* __restrict__ y_pred, int T, int base, int my_y, int lane,
    unsigned &m, int &n,
    float &a0, float &a1, float &a2, float &a3)
{
    int l0 = __ffs(m) - 1; m &= m - 1;
    int l1 = 32, l2 = 32, l3 = 32;
    if (m) { l1 = __ffs(m) - 1; m &= m - 1; }
    if (m) { l2 = __ffs(m) - 1; m &= m - 1; }
    if (m) { l3 = __ffs(m) - 1; m &= m - 1; }
    n = 1 + (l1 < 32) + (l2 < 32) + (l3 < 32);

    int yv0 = __shfl_sync(FULL, my_y, l0);
    int yv1 = __shfl_sync(FULL, my_y, l1 & 31); if (l1 == 32) yv1 = 0;
    int yv2 = __shfl_sync(FULL, my_y, l2 & 31); if (l2 == 32) yv2 = 0;
    int yv3 = __shfl_sync(FULL, my_y, l3 & 31); if (l3 == 32) yv3 = 0;

    const float* r0p = y_pred + (size_t)(base + (l0 & 31)) * (size_t)T;
    const float* r1p = y_pred + (size_t)(base + (l1 & 31)) * (size_t)T;
    const float* r2p = y_pred + (size_t)(base + (l2 & 31)) * (size_t)T;
    const float* r3p = y_pred + (size_t)(base + (l3 & 31)) * (size_t)T;

    const float4* p0 = (const float4*)r0p;
    const float4* p1 = (const float4*)r1p;
    const float4* p2 = (const float4*)r2p;
    const float4* p3 = (const float4*)r3p;

    const int nf0 = yv0 >> 2, nf1 = yv1 >> 2, nf2 = yv2 >> 2, nf3 = yv3 >> 2;

    a0 = 0.0f; a1 = 0.0f; a2 = 0.0f; a3 = 0.0f;

    // y < 512 -> nf <= 128 -> exactly 4 predicated iterations per row
    #pragma unroll
    for (int u = 0; u < 4; ++u) {
        const int j = lane + u * 32;
        if (j < nf0) { float4 v = __ldg(&p0[j]); a0 += (v.x + v.y) + (v.z + v.w); }
        if (j < nf1) { float4 v = __ldg(&p1[j]); a1 += (v.x + v.y) + (v.z + v.w); }
        if (j < nf2) { float4 v = __ldg(&p2[j]); a2 += (v.x + v.y) + (v.z + v.w); }
        if (j < nf3) { float4 v = __ldg(&p3[j]); a3 += (v.x + v.y) + (v.z + v.w); }
    }
    if (lane < (yv0 & 3)) a0 += __ldg(r0p + (nf0 << 2) + lane);
    if (lane < (yv1 & 3)) a1 += __ldg(r1p + (nf1 << 2) + lane);
    if (lane < (yv2 & 3)) a2 += __ldg(r2p + (nf2 << 2) + lane);
    if (lane < (yv3 & 3)) a3 += __ldg(r3p + (nf3 << 2) + lane);
}

// Quad reduce: 11 shfls, 4 row sums replicated per 8-lane group.
__device__ __forceinline__ void quad_reduce(
    int lane, int n, float a0, float a1, float a2, float a3, float &wsum)
{
    a0 += __shfl_xor_sync(FULL, a0, 16);
    a1 += __shfl_xor_sync(FULL, a1, 16);
    a2 += __shfl_xor_sync(FULL, a2, 16);
    a3 += __shfl_xor_sync(FULL, a3, 16);
    a0 += __shfl_xor_sync(FULL, a0, 8);
    a1 += __shfl_xor_sync(FULL, a1, 8);
    a2 += __shfl_xor_sync(FULL, a2, 8);
    a3 += __shfl_xor_sync(FULL, a3, 8);

    float c = (lane & 16) ? ((lane & 8) ? a3 : a2)
                          : ((lane & 8) ? a1 : a0);
    c += __shfl_xor_sync(FULL, c, 4);
    c += __shfl_xor_sync(FULL, c, 2);
    c += __shfl_xor_sync(FULL, c, 1);

    if ((lane & 7) == 0 && (lane >> 3) < n)
        wsum += -__logf(1.0f - c);
}

__global__ void __launch_bounds__(BLOCK_THREADS, 12)
surv_loss_kernel(const float* __restrict__ y_pred,
                 const int* __restrict__ y,
                 const int* __restrict__ status,
                 float* __restrict__ out,
                 int B, int T)
{
    const int lane  = threadIdx.x & 31;
    const int wib   = threadIdx.x >> 5;
    const int gwarp = blockIdx.x * WARPS_PER_BLOCK + wib;
    const int nwarps = gridDim.x * WARPS_PER_BLOCK;

    float wsum = 0.0f;

    for (int base = gwarp * BATCH; base < B; base += nwarps * BATCH) {
        const int  row   = base + lane;
        const bool valid = row < B;
        const int  my_y  = valid ? __ldg(&y[row]) : 0;
        const int  my_st = valid ? __ldg(&status[row]) : 1;

        // status==1 rows: issue gather early, consume at end of batch
        const bool has_g = valid && (my_st == 1);
        float gval = 1.0f;
        if (has_g) gval = __ldg(y_pred + (size_t)row * (size_t)T + my_y);

        unsigned m = __ballot_sync(FULL, valid && my_st == 0 && my_y > 0);

        while (m) {
            int n; float a0, a1, a2, a3;
            quad_issue(y_pred, T, base, my_y, lane, m, n, a0, a1, a2, a3);
            quad_reduce(lane, n, a0, a1, a2, a3, wsum);
        }

        if (has_g) wsum += -__logf(gval);
    }

    // --- warp reduce of per-lane wsum ---
    #pragma unroll
    for (int o = 16; o > 0; o >>= 1)
        wsum += __shfl_xor_sync(FULL, wsum, o);

    __shared__ float warp_vals[WARPS_PER_BLOCK];
    __shared__ bool  is_last;
    if (lane == 0) warp_vals[wib] = wsum;
    __syncthreads();

    if (threadIdx.x == 0) {
        double s = 0.0;
        #pragma unroll
        for (int w = 0; w < WARPS_PER_BLOCK; ++w) s += (double)warp_vals[w];
        g_partials[blockIdx.x] = s;
        __threadfence();
        unsigned done = atomicAdd(&g_count, 1u);
        is_last = (done == gridDim.x - 1);
    }
    __syncthreads();

    // --- last block reduces all partials (deterministic fixed order) ---
    if (is_last) {
        volatile double* gp = g_partials;
        double s = 0.0;
        for (int i = threadIdx.x; i < (int)gridDim.x; i += BLOCK_THREADS)
            s += gp[i];

        #pragma unroll
        for (int o = 16; o > 0; o >>= 1)
            s += __shfl_down_sync(FULL, s, o);

        __shared__ double sh[WARPS_PER_BLOCK];
        if (lane == 0) sh[wib] = s;
        __syncthreads();

        if (threadIdx.x == 0) {
            double t = 0.0;
            #pragma unroll
            for (int w = 0; w < WARPS_PER_BLOCK; ++w) t += sh[w];
            out[0] = (float)t;
            atomicExch(&g_count, 0u);   // reset for next graph replay
        }
    }
}

extern "C" void kernel_launch(void* const* d_in, const int* in_sizes, int n_in,
                              void* d_out, int out_size)
{
    const float* y_pred = (const float*)d_in[0];
    const int*   y      = (const int*)d_in[1];
    const int*   status = (const int*)d_in[2];
    float*       out    = (float*)d_out;

    const int B = in_sizes[1];
    const int T = in_sizes[0] / B;

    surv_loss_kernel<<<NBLOCKS, BLOCK_THREADS>>>(y_pred, y, status, out, B, T);
}

// round 8
// speedup vs baseline: 1.2129x; 1.2129x over previous
#include <cuda_runtime.h>
#include <cstdint>

// -----------------------------------------------------------------------------
// Surv_Loss (R8): R4 config EXACTLY (256thr, no occ cap, grid 1024, 32-row
// batches, quad rounds) with the per-round reduce chain cut from depth-5 shfl
// tree (~330cyc, measured as the DRAM duty-cycle killer) to depth-3:
//   - fold each row acc via xor16/xor8/xor4 (12 shfls, ILP 4, dep depth 3)
//   - STS the 4 surviving partials per row to a per-warp smem slot (no wait)
//   - ONE reduce pass per batch: lane l -> LDS.128 slot l + 3 adds + logf
// Fused final reduction unchanged (threadfence last-block, double accum).
// -----------------------------------------------------------------------------

#define BLOCK_THREADS 256
#define WARPS_PER_BLOCK 8
#define NBLOCKS 1024
#define BATCH 32
#define MAX_PARTIALS 2048
#define FULL 0xFFFFFFFFu

__device__ double g_partials[MAX_PARTIALS];
__device__ unsigned int g_count = 0;

__global__ void __launch_bounds__(BLOCK_THREADS)
surv_loss_kernel(const float* __restrict__ y_pred,
                 const int* __restrict__ y,
                 const int* __restrict__ status,
                 float* __restrict__ out,
                 int B, int T)
{
    const int lane  = threadIdx.x & 31;
    const int wib   = threadIdx.x >> 5;
    const int gwarp = blockIdx.x * WARPS_PER_BLOCK + wib;
    const int nwarps = gridDim.x * WARPS_PER_BLOCK;

    // per-warp slots: 32 rows x 4 partials (float4 each)
    __shared__ float4 sm_part[WARPS_PER_BLOCK][BATCH];

    float wsum = 0.0f;

    for (int base = gwarp * BATCH; base < B; base += nwarps * BATCH) {
        const int  row   = base + lane;
        const bool valid = row < B;
        const int  my_y  = valid ? __ldg(&y[row]) : 0;
        const int  my_st = valid ? __ldg(&status[row]) : 1;

        // status==1 rows: issue gather early, consume at end of batch
        const bool has_g = valid && (my_st == 1);
        float gval = 1.0f;
        if (has_g) gval = __ldg(y_pred + (size_t)row * (size_t)T + my_y);

        unsigned m = __ballot_sync(FULL, valid && my_st == 0 && my_y > 0);
        const int count = __popc(m);
        int slot = 0;

        while (m) {
            int l0 = __ffs(m) - 1; m &= m - 1;
            int l1 = 32, l2 = 32, l3 = 32;
            if (m) { l1 = __ffs(m) - 1; m &= m - 1; }
            if (m) { l2 = __ffs(m) - 1; m &= m - 1; }
            if (m) { l3 = __ffs(m) - 1; m &= m - 1; }
            const int n = 1 + (l1 < 32) + (l2 < 32) + (l3 < 32);

            int yv0 = __shfl_sync(FULL, my_y, l0);
            int yv1 = __shfl_sync(FULL, my_y, l1 & 31); if (l1 == 32) yv1 = 0;
            int yv2 = __shfl_sync(FULL, my_y, l2 & 31); if (l2 == 32) yv2 = 0;
            int yv3 = __shfl_sync(FULL, my_y, l3 & 31); if (l3 == 32) yv3 = 0;

            const float* r0p = y_pred + (size_t)(base + (l0 & 31)) * (size_t)T;
            const float* r1p = y_pred + (size_t)(base + (l1 & 31)) * (size_t)T;
            const float* r2p = y_pred + (size_t)(base + (l2 & 31)) * (size_t)T;
            const float* r3p = y_pred + (size_t)(base + (l3 & 31)) * (size_t)T;

            const float4* p0 = (const float4*)r0p;
            const float4* p1 = (const float4*)r1p;
            const float4* p2 = (const float4*)r2p;
            const float4* p3 = (const float4*)r3p;

            const int nf0 = yv0 >> 2, nf1 = yv1 >> 2, nf2 = yv2 >> 2, nf3 = yv3 >> 2;

            float a0 = 0.0f, a1 = 0.0f, a2 = 0.0f, a3 = 0.0f;

            // y < 512 -> nf <= 128 -> exactly 4 predicated iterations per row
            #pragma unroll
            for (int u = 0; u < 4; ++u) {
                const int j = lane + u * 32;
                if (j < nf0) { float4 v = __ldg(&p0[j]); a0 += (v.x + v.y) + (v.z + v.w); }
                if (j < nf1) { float4 v = __ldg(&p1[j]); a1 += (v.x + v.y) + (v.z + v.w); }
                if (j < nf2) { float4 v = __ldg(&p2[j]); a2 += (v.x + v.y) + (v.z + v.w); }
                if (j < nf3) { float4 v = __ldg(&p3[j]); a3 += (v.x + v.y) + (v.z + v.w); }
            }
            if (lane < (yv0 & 3)) a0 += __ldg(r0p + (nf0 << 2) + lane);
            if (lane < (yv1 & 3)) a1 += __ldg(r1p + (nf1 << 2) + lane);
            if (lane < (yv2 & 3)) a2 += __ldg(r2p + (nf2 << 2) + lane);
            if (lane < (yv3 & 3)) a3 += __ldg(r3p + (nf3 << 2) + lane);

            // depth-3 fold: after xor16/8/4, a_i[lane] = sum over lanes == lane (mod 4)
            a0 += __shfl_xor_sync(FULL, a0, 16);
            a1 += __shfl_xor_sync(FULL, a1, 16);
            a2 += __shfl_xor_sync(FULL, a2, 16);
            a3 += __shfl_xor_sync(FULL, a3, 16);
            a0 += __shfl_xor_sync(FULL, a0, 8);
            a1 += __shfl_xor_sync(FULL, a1, 8);
            a2 += __shfl_xor_sync(FULL, a2, 8);
            a3 += __shfl_xor_sync(FULL, a3, 8);
            a0 += __shfl_xor_sync(FULL, a0, 4);
            a1 += __shfl_xor_sync(FULL, a1, 4);
            a2 += __shfl_xor_sync(FULL, a2, 4);
            a3 += __shfl_xor_sync(FULL, a3, 4);

            // lane group g = lane>>3 handles row g of this round; lanes with
            // (lane&7)<4 store partial (lane&3) as one scalar STS each.
            const int g = lane >> 3;
            if (g < n && (lane & 7) < 4) {
                float sel = (g & 2) ? ((g & 1) ? a3 : a2)
                                    : ((g & 1) ? a1 : a0);
                ((float*)&sm_part[wib][slot + g])[lane & 3] = sel;
            }
            slot += n;
        }

        __syncwarp(FULL);

        // one reduce pass per batch: lane l owns slot l
        if (lane < count) {
            float4 v = sm_part[wib][lane];
            float c = (v.x + v.y) + (v.z + v.w);
            wsum += -__logf(1.0f - c);
        }

        if (has_g) wsum += -__logf(gval);
        __syncwarp(FULL);
    }

    // --- warp reduce of per-lane wsum ---
    #pragma unroll
    for (int o = 16; o > 0; o >>= 1)
        wsum += __shfl_xor_sync(FULL, wsum, o);

    __shared__ float warp_vals[WARPS_PER_BLOCK];
    __shared__ bool  is_last;
    if (lane == 0) warp_vals[wib] = wsum;
    __syncthreads();

    if (threadIdx.x == 0) {
        double s = 0.0;
        #pragma unroll
        for (int w = 0; w < WARPS_PER_BLOCK; ++w) s += (double)warp_vals[w];
        g_partials[blockIdx.x] = s;
        __threadfence();
        unsigned done = atomicAdd(&g_count, 1u);
        is_last = (done == gridDim.x - 1);
    }
    __syncthreads();

    // --- last block reduces all partials (deterministic fixed order) ---
    if (is_last) {
        volatile double* gp = g_partials;
        double s = 0.0;
        for (int i = threadIdx.x; i < (int)gridDim.x; i += BLOCK_THREADS)
            s += gp[i];

        #pragma unroll
        for (int o = 16; o > 0; o >>= 1)
            s += __shfl_down_sync(FULL, s, o);

        __shared__ double sh[WARPS_PER_BLOCK];
        if (lane == 0) sh[wib] = s;
        __syncthreads();

        if (threadIdx.x == 0) {
            double t = 0.0;
            #pragma unroll
            for (int w = 0; w < WARPS_PER_BLOCK; ++w) t += sh[w];
            out[0] = (float)t;
            atomicExch(&g_count, 0u);   // reset for next graph replay
        }
    }
}

extern "C" void kernel_launch(void* const* d_in, const int* in_sizes, int n_in,
                              void* d_out, int out_size)
{
    const float* y_pred = (const float*)d_in[0];
    const int*   y      = (const int*)d_in[1];
    const int*   status = (const int*)d_in[2];
    float*       out    = (float*)d_out;

    const int B = in_sizes[1];
    const int T = in_sizes[0] / B;

    surv_loss_kernel<<<NBLOCKS, BLOCK_THREADS>>>(y_pred, y, status, out, B, T);
}